// round 7
// baseline (speedup 1.0000x reference)
#include <cuda_runtime.h>

#define BB 128
#define MM 60
#define HMM 30             // labels per half
#define FG 19
#define NCc 80
#define CELLS (FG*FG)      // 361
#define NBLK (BB*3)        // 384
#define NTHR 768
#define NWRP 24

__device__ double g_acc[6];   // zero-initialized at load; restored each launch
__device__ int    g_done;

// anchors / 32 (exact in fp32)
__constant__ float c_aw[9] = {0.3125f, 0.5f,     1.03125f, 0.9375f, 1.9375f,
                              1.84375f, 3.625f,  4.875f,   11.65625f};
__constant__ float c_ah[9] = {0.40625f, 0.9375f, 0.71875f, 1.90625f, 1.40625f,
                              3.71875f, 2.8125f, 6.1875f,  10.1875f};

// One block per (batch, anchor). 768 threads: two half-lanes per cell,
// each covering 30 of the 60 truth labels in the ignore-mask IoU pass.
__global__ void __launch_bounds__(NTHR, 2)
k_fused(const float* __restrict__ out, const float* __restrict__ labels,
        float* __restrict__ o) {
    int b = blockIdx.x;
    int anc = blockIdx.y;
    int tid = threadIdx.x;
    int cell = (tid < 384) ? tid : (tid - 384);   // cell index (valid if <361)
    int half = (tid < 384) ? 0 : 1;

    __shared__ float  sL[MM * 5];
    __shared__ float4 sTc[MM];        // truth corners x1,y1,x2,y2
    __shared__ float  sTb[MM];        // truth area (bA)
    __shared__ float  sPay[MM][6];    // txf,tyf,twt,tht,sc,cls
    __shared__ int    sCellI[CELLS];  // winning label per cell (atomicMax), -1 none
    __shared__ float  sDD[CELLS];     // secondary half's dd partial
    __shared__ short  sMm[MM];
    __shared__ short  sMloc[MM];
    __shared__ int    sN;
    __shared__ float  sRed[NWRP][5];

    // ---- prefetch channel values (latency overlaps label load + scatter) ----
    float x0 = 0.f, y0 = 0.f, zw = 0.f, zh = 0.f, zo = 0.f;
    if (cell < CELLS) {
        size_t base = ((size_t)(b * 255 + anc * 85)) * CELLS + cell;
        x0 = __ldg(&out[base]);
        y0 = __ldg(&out[base + CELLS]);
        zw = __ldg(&out[base + 2 * CELLS]);
        zh = __ldg(&out[base + 3 * CELLS]);
        if (half == 0) zo = __ldg(&out[base + 4 * CELLS]);
    }

    if (tid == 0) sN = 0;
    for (int t = tid; t < MM * 5; t += NTHR) sL[t] = labels[b * (MM * 5) + t];
    for (int t = tid; t < CELLS; t += NTHR) sCellI[t] = -1;
    __syncthreads();

    // ---- per-label truth boxes + anchor matching + atomicMax claim ----
    int myflat = -1;
    if (tid < MM) {
        int m = tid;
        float l0 = sL[m*5], l1 = sL[m*5+1], l2 = sL[m*5+2], l3 = sL[m*5+3], l4 = sL[m*5+4];
        bool valid = (l0 + l1 + l2 + l3 + l4) > 0.0f;
        float tx = floorf(l0 * 0.03125f);
        float ty = floorf(l1 * 0.03125f);
        float tw = floorf((l2 - l0) * 0.03125f);
        float th = floorf((l3 - l1) * 0.03125f);
        float ta = tw * th;

        if (valid) {
            float hw = tw * 0.5f, hh = th * 0.5f;
            sTc[m] = make_float4(tx - hw, ty - hh, tx + hw, ty + hh);
            sTb[m] = ta;
        } else {
            sTc[m] = make_float4(3e18f, 3e18f, 3e18f, 3e18f);
            sTb[m] = 0.f;
        }

        float best = -1.0f; int bi = 0;
        #pragma unroll
        for (int k = 0; k < 9; k++) {
            float mw = fminf(tw, c_aw[k]);
            float mh = fminf(th, c_ah[k]);
            float inter = (mw > 0.f && mh > 0.f) ? mw * mh : 0.f;
            float aiou = inter / (ta + c_aw[k] * c_ah[k] - inter);
            if (aiou > best) { best = aiou; bi = k; }
        }

        if (valid && bi == 6 + anc) {
            int ti = (int)tx, tj = (int)ty;
            if (ti >= 0 && ti < FG && tj >= 0 && tj < FG) {
                myflat = tj * FG + ti;
                sPay[m][0] = tx - (float)((int)tx);
                sPay[m][1] = ty - (float)((int)ty);
                sPay[m][2] = logf(tw / c_aw[6 + anc] + 1e-16f);
                sPay[m][3] = logf(th / c_ah[6 + anc] + 1e-16f);
                sPay[m][4] = sqrtf(2.0f - ta / 361.0f);
                sPay[m][5] = l4;
                atomicMax(&sCellI[myflat], m);   // last-label-wins == max m
            }
        }
    }
    __syncthreads();

    // winners append (list consumed only after the next barrier)
    if (tid < MM && myflat >= 0 && sCellI[myflat] == tid) {
        int p = atomicAdd(&sN, 1);
        sMm[p] = (short)tid;
        sMloc[p] = (short)myflat;
    }

    // ---- half IoU loop: dd = max over 30 labels of (3*inter - bA) ----
    float ax1 = 0.f, ay1 = 0.f, ax2 = 0.f, ay2 = 0.f, pA = 1.f;
    float sx = 0.f, sy = 0.f;
    float dd = -1e30f;
    if (cell < CELLS) {
        int j = cell / FG, i = cell - j * FG;
        float caw = c_aw[6 + anc], cah = c_ah[6 + anc];
        sx = 1.f / (1.f + __expf(-x0));
        sy = 1.f / (1.f + __expf(-y0));
        float pw = __expf(zw) * caw;
        float ph = __expf(zh) * cah;
        float px = sx + (float)i;
        float py = sy + (float)j;
        ax1 = px - 0.5f * pw; ax2 = px + 0.5f * pw;
        ay1 = py - 0.5f * ph; ay2 = py + 0.5f * ph;
        pA = pw * ph;

        int m0 = half * HMM;
        float d0 = -1e30f, d1 = -1e30f;
        #pragma unroll 6
        for (int m = m0; m < m0 + HMM; m += 2) {
            {
                float4 c = sTc[m];   float bA = sTb[m];
                float w = fminf(ax2, c.z) - fmaxf(ax1, c.x);
                float h = fminf(ay2, c.w) - fmaxf(ay1, c.y);
                float inter = fmaxf(w, 0.f) * fmaxf(h, 0.f);
                d0 = fmaxf(d0, __fmaf_rn(inter, 3.f, -bA));
            }
            {
                float4 c = sTc[m+1]; float bA = sTb[m+1];
                float w = fminf(ax2, c.z) - fmaxf(ax1, c.x);
                float h = fminf(ay2, c.w) - fmaxf(ay1, c.y);
                float inter = fmaxf(w, 0.f) * fmaxf(h, 0.f);
                d1 = fmaxf(d1, __fmaf_rn(inter, 3.f, -bA));
            }
        }
        dd = fmaxf(d0, d1);
        if (half == 1) sDD[cell] = dd;
    }
    __syncthreads();   // sDD + winners list complete

    // ---- losses (primary half only) ----
    float a_xy = 0.f, a_wh = 0.f, a_obj = 0.f, a_cls = 0.f, a_l2 = 0.f;

    if (half == 0 && cell < CELLS) {
        float ddt = fmaxf(dd, sDD[cell]);
        int pm = sCellI[cell];
        float so = 1.f / (1.f + __expf(-zo));
        if (pm >= 0) {
            const float* P = &sPay[pm][0];
            float txf = P[0], tyf = P[1], twt = P[2], tht = P[3], sc = P[4];
            float w2 = sc * sc;
            float lpx = fmaxf(__logf(sx), -100.f);
            float lqx = fmaxf(__logf(1.f - sx), -100.f);
            float lpy = fmaxf(__logf(sy), -100.f);
            float lqy = fmaxf(__logf(1.f - sy), -100.f);
            a_xy += -w2 * (txf * lpx + (1.f - txf) * lqx)
                    - w2 * (tyf * lpy + (1.f - tyf) * lqy);
            float dw = zw - twt, dh = zh - tht;
            float whs = w2 * (dw * dw + dh * dh);
            a_wh += 0.5f * whs;
            a_obj += -fmaxf(__logf(so), -100.f);
            float ex = sx - txf, ey = sy - tyf, eo = so - 1.f;
            a_l2 += ex * ex + ey * ey + whs + eo * eo;
        } else if (ddt <= pA) {   // best_iou <= 0.5
            a_obj += -fmaxf(__logf(1.f - so), -100.f);
            a_l2 += so * so;
        }
    }

    // ---- class loss: one warp per matched cell (24 warps) ----
    int wid = tid >> 5, lane = tid & 31;
    int n = sN;
    for (int w = wid; w < n; w += NWRP) {
        int m = sMm[w];
        int idx = sMloc[w];
        int cls = (int)sPay[m][5];
        size_t cbase = ((size_t)(b * 255 + anc * 85 + 5)) * CELLS + idx;
        #pragma unroll
        for (int r = 0; r < 3; r++) {
            int cc = lane + r * 32;
            if (cc < NCc) {
                float z = __ldg(&out[cbase + (size_t)cc * CELLS]);
                float p = 1.f / (1.f + __expf(-z));
                float lp = fmaxf(__logf(p), -100.f);
                float lq = fmaxf(__logf(1.f - p), -100.f);
                float t = (cc == cls) ? 1.f : 0.f;
                a_cls += -(t * lp + (1.f - t) * lq);
                float e = p - t;
                a_l2 += e * e;
            }
        }
    }

    // ---- reduce: warp shuffle -> smem -> thread 0 -> double atomics ----
    unsigned msk = 0xffffffffu;
    for (int off = 16; off > 0; off >>= 1) {
        a_xy  += __shfl_down_sync(msk, a_xy, off);
        a_wh  += __shfl_down_sync(msk, a_wh, off);
        a_obj += __shfl_down_sync(msk, a_obj, off);
        a_cls += __shfl_down_sync(msk, a_cls, off);
        a_l2  += __shfl_down_sync(msk, a_l2, off);
    }
    if (lane == 0) {
        sRed[wid][0] = a_xy; sRed[wid][1] = a_wh; sRed[wid][2] = a_obj;
        sRed[wid][3] = a_cls; sRed[wid][4] = a_l2;
    }
    __syncthreads();
    if (tid == 0) {
        float r0 = 0.f, r1 = 0.f, r2 = 0.f, r3 = 0.f, r4 = 0.f;
        #pragma unroll
        for (int w = 0; w < NWRP; w++) {
            r0 += sRed[w][0]; r1 += sRed[w][1]; r2 += sRed[w][2];
            r3 += sRed[w][3]; r4 += sRed[w][4];
        }
        atomicAdd(&g_acc[1], (double)r0);
        atomicAdd(&g_acc[2], (double)r1);
        atomicAdd(&g_acc[3], (double)r2);
        atomicAdd(&g_acc[4], (double)r3);
        atomicAdd(&g_acc[5], (double)r4);
        __threadfence();
        int d = atomicAdd(&g_done, 1);
        if (d == NBLK - 1) {
            double xy = atomicAdd(&g_acc[1], 0.0);
            double wh = atomicAdd(&g_acc[2], 0.0);
            double ob = atomicAdd(&g_acc[3], 0.0);
            double cl = atomicAdd(&g_acc[4], 0.0);
            double l2 = atomicAdd(&g_acc[5], 0.0);
            o[0] = (float)(xy + wh + ob + cl);
            o[1] = (float)xy;
            o[2] = (float)wh;
            o[3] = (float)ob;
            o[4] = (float)cl;
            o[5] = (float)l2;
            g_acc[1] = 0.0; g_acc[2] = 0.0; g_acc[3] = 0.0;
            g_acc[4] = 0.0; g_acc[5] = 0.0;
            g_done = 0;
        }
    }
}

extern "C" void kernel_launch(void* const* d_in, const int* in_sizes, int n_in,
                              void* d_out, int out_size) {
    const float* output = (const float*)d_in[0];
    const float* labels = (const float*)d_in[1];
    float* o = (float*)d_out;
    (void)in_sizes; (void)n_in; (void)out_size;

    dim3 grid(BB, 3);
    k_fused<<<grid, NTHR>>>(output, labels, o);
}

// round 8
// speedup vs baseline: 1.2243x; 1.2243x over previous
#include <cuda_runtime.h>

#define BB 128
#define MM 60
#define FG 19
#define NCc 80
#define CELLS (FG*FG)      // 361
#define NBLK (BB*3)        // 384
#define NTHR 384
#define NWRP 12

__device__ double g_acc[6];   // zero-initialized at load; restored each launch
__device__ int    g_done;

// anchors / 32 (exact in fp32)
__constant__ float c_aw[9] = {0.3125f, 0.5f,     1.03125f, 0.9375f, 1.9375f,
                              1.84375f, 3.625f,  4.875f,   11.65625f};
__constant__ float c_ah[9] = {0.40625f, 0.9375f, 0.71875f, 1.90625f, 1.40625f,
                              3.71875f, 2.8125f, 6.1875f,  10.1875f};

// One block per (batch, anchor). 384 threads, 4 blocks/SM.
__global__ void __launch_bounds__(NTHR, 4)
k_fused(const float* __restrict__ out, const float* __restrict__ labels,
        float* __restrict__ o) {
    int b = blockIdx.x;
    int anc = blockIdx.y;
    int tid = threadIdx.x;
    int wid = tid >> 5, lane = tid & 31;

    __shared__ float4 sTc[MM];        // truth corners x1,y1,x2,y2
    __shared__ float  sTb[MM];        // truth area (bA)
    __shared__ float  sPayR[MM][6];   // raw: tx,ty,tw,th,ta,l4
    __shared__ int    sCellI[CELLS];  // winning label per cell (atomicMax), -1
    __shared__ short  sMm[MM];
    __shared__ short  sMloc[MM];
    __shared__ int    sN;
    __shared__ float  sRed[NWRP][5];

    // ---- prefetch this cell's 5 channel values ----
    float x0 = 0.f, y0 = 0.f, zw = 0.f, zh = 0.f, zo = 0.f;
    if (tid < CELLS) {
        size_t base = ((size_t)(b * 255 + anc * 85)) * CELLS + tid;
        x0 = __ldg(&out[base]);
        y0 = __ldg(&out[base + CELLS]);
        zw = __ldg(&out[base + 2 * CELLS]);
        zh = __ldg(&out[base + 3 * CELLS]);
        zo = __ldg(&out[base + 4 * CELLS]);
    }

    if (tid == 0) sN = 0;
    for (int t = tid; t < CELLS; t += NTHR) sCellI[t] = -1;

    // ---- per-label truth boxes + anchor matching (threads 0..59) ----
    int myflat = -1;
    if (tid < MM) {
        int m = tid;
        const float* L = labels + (size_t)(b * MM + m) * 5;
        float l0 = __ldg(L), l1 = __ldg(L+1), l2 = __ldg(L+2), l3 = __ldg(L+3), l4 = __ldg(L+4);
        bool valid = (l0 + l1 + l2 + l3 + l4) > 0.0f;
        float tx = floorf(l0 * 0.03125f);
        float ty = floorf(l1 * 0.03125f);
        float tw = floorf((l2 - l0) * 0.03125f);
        float th = floorf((l3 - l1) * 0.03125f);
        float ta = tw * th;

        if (valid) {
            float hw = tw * 0.5f, hh = th * 0.5f;
            sTc[m] = make_float4(tx - hw, ty - hh, tx + hw, ty + hh);
            sTb[m] = ta;
        } else {
            sTc[m] = make_float4(3e18f, 3e18f, 3e18f, 3e18f);
            sTb[m] = 0.f;
        }

        float best = -1.0f; int bi = 0;
        #pragma unroll
        for (int k = 0; k < 9; k++) {
            float mw = fminf(tw, c_aw[k]);
            float mh = fminf(th, c_ah[k]);
            float inter = (mw > 0.f && mh > 0.f) ? mw * mh : 0.f;
            float aiou = inter / (ta + c_aw[k] * c_ah[k] - inter);
            if (aiou > best) { best = aiou; bi = k; }
        }

        if (valid && bi == 6 + anc) {
            int ti = (int)tx, tj = (int)ty;
            if (ti >= 0 && ti < FG && tj >= 0 && tj < FG) {
                myflat = tj * FG + ti;
                sPayR[m][0] = tx; sPayR[m][1] = ty;
                sPayR[m][2] = tw; sPayR[m][3] = th;
                sPayR[m][4] = ta; sPayR[m][5] = l4;
                atomicMax(&sCellI[myflat], m);   // last-label-wins == max m
            }
        }
    }
    __syncthreads();

    // winners append to the matched list
    if (tid < MM && myflat >= 0 && sCellI[myflat] == tid) {
        int p = atomicAdd(&sN, 1);
        sMm[p] = (short)tid;
        sMloc[p] = (short)myflat;
    }
    __syncthreads();

    // ---- class prefetch: warp `wid` takes matched entry `wid`; its 3 LDGs
    //      are issued NOW so the IoU loop below hides their latency ----
    int n = sN;
    float cz0 = 0.f, cz1 = 0.f, cz2 = 0.f;
    int mycls = -1;
    bool have = (wid < n);
    size_t cbase0 = 0;
    if (have) {
        int m = sMm[wid];
        int idx = sMloc[wid];
        mycls = (int)sPayR[m][5];
        cbase0 = ((size_t)(b * 255 + anc * 85 + 5)) * CELLS + idx;
        cz0 = __ldg(&out[cbase0 + (size_t)lane * CELLS]);
        cz1 = __ldg(&out[cbase0 + (size_t)(lane + 32) * CELLS]);
        if (lane < 16) cz2 = __ldg(&out[cbase0 + (size_t)(lane + 64) * CELLS]);
    }

    // ---- per-cell IoU ignore-mask + xy/wh/obj losses ----
    float a_xy = 0.f, a_wh = 0.f, a_obj = 0.f, a_cls = 0.f, a_l2 = 0.f;

    if (tid < CELLS) {
        int idx = tid;
        int j = idx / FG, i = idx - j * FG;
        float caw = c_aw[6 + anc], cah = c_ah[6 + anc];

        float sx = 1.f / (1.f + __expf(-x0));
        float sy = 1.f / (1.f + __expf(-y0));
        float pw = __expf(zw) * caw;
        float ph = __expf(zh) * cah;
        float px = sx + (float)i;
        float py = sy + (float)j;
        float ax1 = px - 0.5f * pw, ax2 = px + 0.5f * pw;
        float ay1 = py - 0.5f * ph, ay2 = py + 0.5f * ph;
        float pA = pw * ph;

        float d0 = -1e30f, d1 = -1e30f, d2 = -1e30f, d3 = -1e30f;
        #pragma unroll 4
        for (int m = 0; m < MM; m += 4) {
            {
                float4 c = sTc[m];   float bA = sTb[m];
                float w = fminf(ax2, c.z) - fmaxf(ax1, c.x);
                float h = fminf(ay2, c.w) - fmaxf(ay1, c.y);
                float inter = fmaxf(w, 0.f) * fmaxf(h, 0.f);
                d0 = fmaxf(d0, __fmaf_rn(inter, 3.f, -bA));
            }
            {
                float4 c = sTc[m+1]; float bA = sTb[m+1];
                float w = fminf(ax2, c.z) - fmaxf(ax1, c.x);
                float h = fminf(ay2, c.w) - fmaxf(ay1, c.y);
                float inter = fmaxf(w, 0.f) * fmaxf(h, 0.f);
                d1 = fmaxf(d1, __fmaf_rn(inter, 3.f, -bA));
            }
            {
                float4 c = sTc[m+2]; float bA = sTb[m+2];
                float w = fminf(ax2, c.z) - fmaxf(ax1, c.x);
                float h = fminf(ay2, c.w) - fmaxf(ay1, c.y);
                float inter = fmaxf(w, 0.f) * fmaxf(h, 0.f);
                d2 = fmaxf(d2, __fmaf_rn(inter, 3.f, -bA));
            }
            {
                float4 c = sTc[m+3]; float bA = sTb[m+3];
                float w = fminf(ax2, c.z) - fmaxf(ax1, c.x);
                float h = fminf(ay2, c.w) - fmaxf(ay1, c.y);
                float inter = fmaxf(w, 0.f) * fmaxf(h, 0.f);
                d3 = fmaxf(d3, __fmaf_rn(inter, 3.f, -bA));
            }
        }
        float dd = fmaxf(fmaxf(d0, d1), fmaxf(d2, d3));

        int pm = sCellI[idx];
        float so = 1.f / (1.f + __expf(-zo));
        if (pm >= 0) {
            // heavy payload math only for matched cells (<=60/block)
            float tx = sPayR[pm][0], ty = sPayR[pm][1];
            float tw = sPayR[pm][2], th = sPayR[pm][3], ta = sPayR[pm][4];
            float txf = tx - (float)((int)tx);
            float tyf = ty - (float)((int)ty);
            float twt = logf(tw / c_aw[6 + anc] + 1e-16f);
            float tht = logf(th / c_ah[6 + anc] + 1e-16f);
            float w2 = 2.0f - ta / 361.0f;   // sc^2 directly (no sqrt needed)
            float lpx = fmaxf(__logf(sx), -100.f);
            float lqx = fmaxf(__logf(1.f - sx), -100.f);
            float lpy = fmaxf(__logf(sy), -100.f);
            float lqy = fmaxf(__logf(1.f - sy), -100.f);
            a_xy += -w2 * (txf * lpx + (1.f - txf) * lqx)
                    - w2 * (tyf * lpy + (1.f - tyf) * lqy);
            float dw = zw - twt, dh = zh - tht;
            float whs = w2 * (dw * dw + dh * dh);
            a_wh += 0.5f * whs;
            a_obj += -fmaxf(__logf(so), -100.f);
            float ex = sx - txf, ey = sy - tyf, eo = so - 1.f;
            a_l2 += ex * ex + ey * ey + whs + eo * eo;
        } else if (dd <= pA) {   // best_iou <= 0.5
            a_obj += -fmaxf(__logf(1.f - so), -100.f);
            a_l2 += so * so;
        }
    }

    // ---- class math for the prefetched entry ----
    if (have) {
        {
            float p = 1.f / (1.f + __expf(-cz0));
            float lp = fmaxf(__logf(p), -100.f);
            float lq = fmaxf(__logf(1.f - p), -100.f);
            float t = (lane == mycls) ? 1.f : 0.f;
            a_cls += -(t * lp + (1.f - t) * lq);
            float e = p - t; a_l2 += e * e;
        }
        {
            float p = 1.f / (1.f + __expf(-cz1));
            float lp = fmaxf(__logf(p), -100.f);
            float lq = fmaxf(__logf(1.f - p), -100.f);
            float t = (lane + 32 == mycls) ? 1.f : 0.f;
            a_cls += -(t * lp + (1.f - t) * lq);
            float e = p - t; a_l2 += e * e;
        }
        if (lane < 16) {
            float p = 1.f / (1.f + __expf(-cz2));
            float lp = fmaxf(__logf(p), -100.f);
            float lq = fmaxf(__logf(1.f - p), -100.f);
            float t = (lane + 64 == mycls) ? 1.f : 0.f;
            a_cls += -(t * lp + (1.f - t) * lq);
            float e = p - t; a_l2 += e * e;
        }
    }

    // ---- leftover matched entries (n > NWRP), rare slow path ----
    for (int w = NWRP + wid; w < n; w += NWRP) {
        int m = sMm[w];
        int idx = sMloc[w];
        int cls = (int)sPayR[m][5];
        size_t cbase = ((size_t)(b * 255 + anc * 85 + 5)) * CELLS + idx;
        #pragma unroll
        for (int r = 0; r < 3; r++) {
            int cc = lane + r * 32;
            if (cc < NCc) {
                float z = __ldg(&out[cbase + (size_t)cc * CELLS]);
                float p = 1.f / (1.f + __expf(-z));
                float lp = fmaxf(__logf(p), -100.f);
                float lq = fmaxf(__logf(1.f - p), -100.f);
                float t = (cc == cls) ? 1.f : 0.f;
                a_cls += -(t * lp + (1.f - t) * lq);
                float e = p - t;
                a_l2 += e * e;
            }
        }
    }

    // ---- reduce: warp shuffle -> smem -> thread 0 -> double atomics ----
    unsigned msk = 0xffffffffu;
    for (int off = 16; off > 0; off >>= 1) {
        a_xy  += __shfl_down_sync(msk, a_xy, off);
        a_wh  += __shfl_down_sync(msk, a_wh, off);
        a_obj += __shfl_down_sync(msk, a_obj, off);
        a_cls += __shfl_down_sync(msk, a_cls, off);
        a_l2  += __shfl_down_sync(msk, a_l2, off);
    }
    if (lane == 0) {
        sRed[wid][0] = a_xy; sRed[wid][1] = a_wh; sRed[wid][2] = a_obj;
        sRed[wid][3] = a_cls; sRed[wid][4] = a_l2;
    }
    __syncthreads();
    if (tid == 0) {
        float r0 = 0.f, r1 = 0.f, r2 = 0.f, r3 = 0.f, r4 = 0.f;
        #pragma unroll
        for (int w = 0; w < NWRP; w++) {
            r0 += sRed[w][0]; r1 += sRed[w][1]; r2 += sRed[w][2];
            r3 += sRed[w][3]; r4 += sRed[w][4];
        }
        atomicAdd(&g_acc[1], (double)r0);
        atomicAdd(&g_acc[2], (double)r1);
        atomicAdd(&g_acc[3], (double)r2);
        atomicAdd(&g_acc[4], (double)r3);
        atomicAdd(&g_acc[5], (double)r4);
        __threadfence();
        int d = atomicAdd(&g_done, 1);
        if (d == NBLK - 1) {
            double xy = atomicAdd(&g_acc[1], 0.0);
            double wh = atomicAdd(&g_acc[2], 0.0);
            double ob = atomicAdd(&g_acc[3], 0.0);
            double cl = atomicAdd(&g_acc[4], 0.0);
            double l2 = atomicAdd(&g_acc[5], 0.0);
            o[0] = (float)(xy + wh + ob + cl);
            o[1] = (float)xy;
            o[2] = (float)wh;
            o[3] = (float)ob;
            o[4] = (float)cl;
            o[5] = (float)l2;
            g_acc[1] = 0.0; g_acc[2] = 0.0; g_acc[3] = 0.0;
            g_acc[4] = 0.0; g_acc[5] = 0.0;
            g_done = 0;
        }
    }
}

extern "C" void kernel_launch(void* const* d_in, const int* in_sizes, int n_in,
                              void* d_out, int out_size) {
    const float* output = (const float*)d_in[0];
    const float* labels = (const float*)d_in[1];
    float* o = (float*)d_out;
    (void)in_sizes; (void)n_in; (void)out_size;

    dim3 grid(BB, 3);
    k_fused<<<grid, NTHR>>>(output, labels, o);
}